// round 1
// baseline (speedup 1.0000x reference)
#include <cuda_runtime.h>
#include <math.h>

// ---------------- problem constants ----------------
namespace {
constexpr int NB   = 4;        // batch
constexpr int CH   = 128;      // channels
constexpr int NSP  = 32768;    // spatial n = 32*32*32
constexpr int GRP  = 4;        // groupnorm groups
constexpr int NH   = 4;        // heads
constexpr int HDIM = 32;       // head dim
constexpr int QKVC = 3 * CH;   // 384
constexpr int GELEM = (CH / GRP) * NSP;   // 1,048,576 elements per (b,g)
constexpr int RED_CHUNKS = 8;             // reduction split per (b,g)
constexpr int CTX_CHUNKS = 16;            // split-K chunks for ctx GEMM
constexpr int CTX_KBLK = NSP / CTX_CHUNKS;// 2048
constexpr int CTXSZ = NB * NH * HDIM * 33; // 16896 (num[32] + Z per row)
}

// ---------------- device scratch (no allocs allowed) ----------------
__device__ float g_part[NB * GRP * RED_CHUNKS * 2];   // per-chunk sum, sumsq
__device__ float g_W1[NB * QKVC * CH];                // folded qkv weight
__device__ float g_b1[NB * QKVC];                     // folded qkv bias
__device__ float g_qkv[(size_t)NB * QKVC * NSP];      // q rows 0..127, exp(k) 128..255, v 256..383
__device__ float g_ctxp[CTX_CHUNKS * CTXSZ];          // split-K partials
__device__ float g_ctx[CTXSZ];                        // combined num + Z
__device__ float g_M[NB * CH * CH];                   // folded (out_w ∘ ctx) matrix

// ---------------- 1) groupnorm partial reductions ----------------
__global__ void reduce_k(const float* __restrict__ x) {
    int bg = blockIdx.x >> 3;        // 0..15  (= b*4+g, contiguous in memory)
    int chunk = blockIdx.x & 7;
    const float4* p = reinterpret_cast<const float4*>(
        x + (size_t)bg * GELEM + (size_t)chunk * (GELEM / RED_CHUNKS));
    int t = threadIdx.x;
    float s = 0.f, q = 0.f;
#pragma unroll 4
    for (int i = 0; i < 128; i++) {
        float4 v = p[t + i * 256];
        s += (v.x + v.y) + (v.z + v.w);
        q += v.x * v.x + v.y * v.y + v.z * v.z + v.w * v.w;
    }
    for (int off = 16; off; off >>= 1) {
        s += __shfl_down_sync(0xffffffffu, s, off);
        q += __shfl_down_sync(0xffffffffu, q, off);
    }
    __shared__ float ss[8], sq[8];
    if ((t & 31) == 0) { ss[t >> 5] = s; sq[t >> 5] = q; }
    __syncthreads();
    if (t == 0) {
        float S = 0.f, Q = 0.f;
        for (int i = 0; i < 8; i++) { S += ss[i]; Q += sq[i]; }
        g_part[blockIdx.x * 2]     = S;
        g_part[blockIdx.x * 2 + 1] = Q;
    }
}

// ---------------- 2) fold groupnorm into qkv weight/bias ----------------
__global__ void prep_k(const float* __restrict__ qkvw,
                       const float* __restrict__ gnw,
                       const float* __restrict__ gnb) {
    int o = blockIdx.x, b = blockIdx.y, c = threadIdx.x;
    int g = c >> 5;
    int bg = b * GRP + g;
    float S = 0.f, Q = 0.f;
#pragma unroll
    for (int ch = 0; ch < RED_CHUNKS; ch++) {
        S += g_part[(bg * RED_CHUNKS + ch) * 2];
        Q += g_part[(bg * RED_CHUNKS + ch) * 2 + 1];
    }
    const float inv = 1.0f / (float)GELEM;
    float mean = S * inv;
    float var  = Q * inv - mean * mean;
    float rstd = rsqrtf(var + 1e-5f);
    float s = rstd * gnw[c];
    float t = gnb[c] - mean * s;
    float w = qkvw[o * CH + c];
    g_W1[(b * QKVC + o) * CH + c] = w * s;
    __shared__ float red[CH];
    red[c] = w * t;
    __syncthreads();
    for (int off = 64; off; off >>= 1) {
        if (c < off) red[c] += red[c + off];
        __syncthreads();
    }
    if (c == 0) g_b1[b * QKVC + o] = red[0];
}

// ---------------- 3/7) SGEMM: 128x128 tile, K=128, 8x8 per thread ----------------
// mode 0: qkv = W1'[b] @ x[b] + b1'[b]   (rows 128..255 -> exp)
// mode 1: out = M[b] @ q[b] + out_bias + x[b]
__global__ void __launch_bounds__(256) gemm_k(int mode,
                                              const float* __restrict__ extB,
                                              const float* __restrict__ extBias,
                                              const float* __restrict__ extResid,
                                              float* __restrict__ extOut) {
    const int N = NSP;
    int b = blockIdx.z;
    const float* A; const float* Bp; float* Cp; const float* bias; const float* resid;
    int expLo, expHi;
    if (mode == 0) {
        A     = g_W1 + b * QKVC * CH;
        Bp    = extB + (size_t)b * CH * N;
        Cp    = g_qkv + (size_t)b * QKVC * N;
        bias  = g_b1 + b * QKVC;
        resid = nullptr;
        expLo = CH; expHi = 2 * CH;
    } else {
        A     = g_M + b * CH * CH;
        Bp    = g_qkv + (size_t)b * QKVC * N;   // q = rows 0..127
        Cp    = extOut + (size_t)b * CH * N;
        bias  = extBias;
        resid = extResid + (size_t)b * CH * N;
        expLo = 1 << 29; expHi = 0;
    }
    __shared__ __align__(16) float As[8][128];
    __shared__ __align__(16) float Bs[8][128];
    int tid = threadIdx.x;
    int tx = tid & 15, ty = tid >> 4;
    int tM = blockIdx.y * 128, tN = blockIdx.x * 128;
    float acc[8][8];
#pragma unroll
    for (int i = 0; i < 8; i++)
#pragma unroll
        for (int j = 0; j < 8; j++) acc[i][j] = 0.f;
    int arow = tid >> 1, acol = (tid & 1) * 4;
    int brow = tid >> 5, bcol = (tid & 31) * 4;
    for (int k0 = 0; k0 < CH; k0 += 8) {
        float4 av = *reinterpret_cast<const float4*>(&A[(tM + arow) * CH + k0 + acol]);
        As[acol + 0][arow] = av.x; As[acol + 1][arow] = av.y;
        As[acol + 2][arow] = av.z; As[acol + 3][arow] = av.w;
        *reinterpret_cast<float4*>(&Bs[brow][bcol]) =
            *reinterpret_cast<const float4*>(&Bp[(size_t)(k0 + brow) * N + tN + bcol]);
        __syncthreads();
#pragma unroll
        for (int k = 0; k < 8; k++) {
            float af[8], bf[8];
            *reinterpret_cast<float4*>(af)     = *reinterpret_cast<const float4*>(&As[k][ty * 8]);
            *reinterpret_cast<float4*>(af + 4) = *reinterpret_cast<const float4*>(&As[k][ty * 8 + 4]);
            *reinterpret_cast<float4*>(bf)     = *reinterpret_cast<const float4*>(&Bs[k][tx * 8]);
            *reinterpret_cast<float4*>(bf + 4) = *reinterpret_cast<const float4*>(&Bs[k][tx * 8 + 4]);
#pragma unroll
            for (int i = 0; i < 8; i++)
#pragma unroll
                for (int j = 0; j < 8; j++) acc[i][j] += af[i] * bf[j];
        }
        __syncthreads();
    }
#pragma unroll
    for (int i = 0; i < 8; i++) {
        int m = tM + ty * 8 + i;
        float bv = bias[m];
        bool dexp = (m >= expLo) && (m < expHi);
#pragma unroll
        for (int j0 = 0; j0 < 8; j0 += 4) {
            size_t off = (size_t)m * N + tN + tx * 8 + j0;
            float4 r;
            r.x = acc[i][j0 + 0] + bv; r.y = acc[i][j0 + 1] + bv;
            r.z = acc[i][j0 + 2] + bv; r.w = acc[i][j0 + 3] + bv;
            if (dexp) { r.x = expf(r.x); r.y = expf(r.y); r.z = expf(r.z); r.w = expf(r.w); }
            if (resid) {
                const float4 rv = *reinterpret_cast<const float4*>(&resid[off]);
                r.x += rv.x; r.y += rv.y; r.z += rv.z; r.w += rv.w;
            }
            *reinterpret_cast<float4*>(&Cp[off]) = r;
        }
    }
}

// ---------------- 4) ctx = exp(k) @ v^T + rowsum(exp(k)), split-K ----------------
__global__ void __launch_bounds__(256) ctx_k() {
    int chunk = blockIdx.x;
    int bh = blockIdx.y;
    int b = bh >> 2, h = bh & 3;
    const float* ek = g_qkv + (size_t)b * QKVC * NSP + (size_t)(CH + h * HDIM) * NSP;
    const float* vv = g_qkv + (size_t)b * QKVC * NSP + (size_t)(2 * CH + h * HDIM) * NSP;
    int k0 = chunk * CTX_KBLK;
    __shared__ __align__(16) float sE[128][33];
    __shared__ __align__(16) float sV[128][33];
    int t = threadIdx.x;
    int d = t & 31, eg = t >> 5;   // eg: warp id -> e-group
    float a0 = 0.f, a1 = 0.f, a2 = 0.f, a3 = 0.f, az = 0.f;
    for (int kk = k0; kk < k0 + CTX_KBLK; kk += 128) {
#pragma unroll
        for (int i = 0; i < 16; i++) {
            int e = t + i * 256;
            int row = e >> 7, kc = e & 127;
            sE[kc][row] = ek[(size_t)row * NSP + kk + kc];
            sV[kc][row] = vv[(size_t)row * NSP + kk + kc];
        }
        __syncthreads();
#pragma unroll 4
        for (int k = 0; k < 128; k++) {
            float a = sE[k][d];
            az += a;
            a0 += a * sV[k][eg];
            a1 += a * sV[k][eg + 8];
            a2 += a * sV[k][eg + 16];
            a3 += a * sV[k][eg + 24];
        }
        __syncthreads();
    }
    float* base = g_ctxp + ((size_t)(chunk * (NB * NH) + bh) * HDIM + d) * 33;
    base[eg]      = a0;
    base[eg + 8]  = a1;
    base[eg + 16] = a2;
    base[eg + 24] = a3;
    if (eg == 0) base[32] = az;
}

// ---------------- 5) combine split-K partials (deterministic) ----------------
__global__ void combine_k() {
    int t = blockIdx.x * blockDim.x + threadIdx.x;
    if (t >= CTXSZ) return;
    float s = 0.f;
#pragma unroll
    for (int ch = 0; ch < CTX_CHUNKS; ch++) s += g_ctxp[ch * CTXSZ + t];
    g_ctx[t] = s;
}

// ---------------- 6) fold out_weight through ctx: M[b][o,hd] ----------------
__global__ void fold_k(const float* __restrict__ outw) {
    int o = blockIdx.x, b = blockIdx.y;
    int hd = threadIdx.x;
    int h = hd >> 5, d = hd & 31;
    __shared__ float sOW[CH];
    sOW[hd] = outw[o * CH + hd];
    __syncthreads();
    const float* nm = g_ctx + (size_t)((b * NH + h) * HDIM + d) * 33;
    float acc = 0.f;
#pragma unroll
    for (int e = 0; e < HDIM; e++) acc += sOW[h * HDIM + e] * nm[e];
    g_M[(b * CH + o) * CH + hd] = acc / nm[32];
}

// ---------------- launch ----------------
extern "C" void kernel_launch(void* const* d_in, const int* in_sizes, int n_in,
                              void* d_out, int out_size) {
    (void)in_sizes; (void)n_in; (void)out_size;
    const float* x    = (const float*)d_in[0];
    const float* gnw  = (const float*)d_in[1];
    const float* gnb  = (const float*)d_in[2];
    const float* qkvw = (const float*)d_in[3];
    const float* outw = (const float*)d_in[4];
    const float* outb = (const float*)d_in[5];
    float* out = (float*)d_out;

    reduce_k<<<NB * GRP * RED_CHUNKS, 256>>>(x);
    prep_k<<<dim3(QKVC, NB), CH>>>(qkvw, gnw, gnb);
    gemm_k<<<dim3(NSP / 128, QKVC / 128, NB), 256>>>(0, x, nullptr, nullptr, nullptr);
    ctx_k<<<dim3(CTX_CHUNKS, NB * NH), 256>>>();
    combine_k<<<(CTXSZ + 255) / 256, 256>>>();
    fold_k<<<dim3(CH, NB), CH>>>(outw);
    gemm_k<<<dim3(NSP / 128, CH / 128, NB), 256>>>(1, nullptr, outb, x, out);
}

// round 2
// speedup vs baseline: 3.2259x; 3.2259x over previous
#include <cuda_runtime.h>
#include <stdint.h>

// ---------------- problem constants ----------------
namespace {
constexpr int NB   = 4;
constexpr int CH   = 128;
constexpr int NSP  = 32768;
constexpr int GRP  = 4;
constexpr int NH   = 4;
constexpr int HDIM = 32;
constexpr int QKVC = 3 * CH;              // 384
constexpr int GELEM = (CH / GRP) * NSP;   // 1,048,576 per (b,g)
constexpr int RED_CHUNKS = 8;
constexpr int NT = NSP / 128;             // 256 n-tiles
constexpr int CTXSZ = NB * NH * HDIM * 33;// 16896 (num[32] + Z per (b,h,d))
}

// ---------------- device scratch ----------------
__device__ float g_part[NB * GRP * RED_CHUNKS * 2];
__device__ float g_W1[NB * QKVC * CH];          // folded qkv weight (gn absorbed)
__device__ float g_b1[NB * QKVC];               // folded qkv bias
__device__ float g_ctxp[(size_t)NT * CTXSZ];    // per n-tile ctx partials
__device__ float g_ctx[CTXSZ];                  // combined
__device__ float g_M[NB * CH * CH];             // out_w folded through ctx
__device__ float g_F[NB * CH * CH];             // M @ Wq'
__device__ float g_fb[NB * CH];                 // M @ bq' + out_bias

// ---------------- helpers ----------------
__device__ __forceinline__ uint32_t f2tf(float f) {
    uint32_t r; asm("cvt.rna.tf32.f32 %0, %1;" : "=r"(r) : "f"(f)); return r;
}
__device__ __forceinline__ float tf32f(float f) {   // tf32-rounded value as float bits
    return __uint_as_float(f2tf(f));
}
__device__ __forceinline__ void mma8(float* c, uint32_t a0, uint32_t a1,
                                     uint32_t a2, uint32_t a3,
                                     uint32_t b0, uint32_t b1) {
    asm volatile(
        "mma.sync.aligned.m16n8k8.row.col.f32.tf32.tf32.f32 "
        "{%0,%1,%2,%3},{%4,%5,%6,%7},{%8,%9},{%0,%1,%2,%3};"
        : "+f"(c[0]), "+f"(c[1]), "+f"(c[2]), "+f"(c[3])
        : "r"(a0), "r"(a1), "r"(a2), "r"(a3), "r"(b0), "r"(b1));
}

// ---------------- 1) groupnorm stats ----------------
__global__ void reduce_k(const float* __restrict__ x) {
    int bg = blockIdx.x >> 3;
    int chunk = blockIdx.x & 7;
    const float4* p = reinterpret_cast<const float4*>(
        x + (size_t)bg * GELEM + (size_t)chunk * (GELEM / RED_CHUNKS));
    int t = threadIdx.x;
    float s = 0.f, q = 0.f;
#pragma unroll 4
    for (int i = 0; i < 128; i++) {
        float4 v = p[t + i * 256];
        s += (v.x + v.y) + (v.z + v.w);
        q += v.x * v.x + v.y * v.y + v.z * v.z + v.w * v.w;
    }
    for (int off = 16; off; off >>= 1) {
        s += __shfl_down_sync(0xffffffffu, s, off);
        q += __shfl_down_sync(0xffffffffu, q, off);
    }
    __shared__ float ss[8], sq[8];
    if ((t & 31) == 0) { ss[t >> 5] = s; sq[t >> 5] = q; }
    __syncthreads();
    if (t == 0) {
        float S = 0.f, Q = 0.f;
        for (int i = 0; i < 8; i++) { S += ss[i]; Q += sq[i]; }
        g_part[blockIdx.x * 2]     = S;
        g_part[blockIdx.x * 2 + 1] = Q;
    }
}

// ---------------- 2) fold gn into qkv weight/bias ----------------
__global__ void prep_k(const float* __restrict__ qkvw,
                       const float* __restrict__ gnw,
                       const float* __restrict__ gnb) {
    int o = blockIdx.x, b = blockIdx.y, c = threadIdx.x;
    int g = c >> 5;
    int bg = b * GRP + g;
    float S = 0.f, Q = 0.f;
#pragma unroll
    for (int ch = 0; ch < RED_CHUNKS; ch++) {
        S += g_part[(bg * RED_CHUNKS + ch) * 2];
        Q += g_part[(bg * RED_CHUNKS + ch) * 2 + 1];
    }
    const float inv = 1.0f / (float)GELEM;
    float mean = S * inv;
    float var  = Q * inv - mean * mean;
    float rstd = rsqrtf(var + 1e-5f);
    float s = rstd * gnw[c];
    float t = gnb[c] - mean * s;
    float w = qkvw[o * CH + c];
    g_W1[(b * QKVC + o) * CH + c] = w * s;
    __shared__ float red[CH];
    red[c] = w * t;
    __syncthreads();
    for (int off = 64; off; off >>= 1) {
        if (c < off) red[c] += red[c + off];
        __syncthreads();
    }
    if (c == 0) g_b1[b * QKVC + o] = red[0];
}

// ---------------- 3) fused kv-gemm + softmax-exp + ctx partials ----------------
// Block: 256 thr (8 warps). Computes rows 128..383 of qkv (k,v) for one
// 128-col n-tile, applies bias (+exp on k), then per head accumulates
// partial ctx = exp(k) @ v^T and Z = rowsum(exp(k)) via tf32 mma.
// Writes ONLY the 4*32*33 partial per (n-tile, b, h). No qkv to global.
__global__ void __launch_bounds__(256) gemm0_k(const float* __restrict__ x) {
    __shared__ float smem[8448];
    float* As = smem;            // [256][20]
    float* Bs = smem + 5120;     // [16][136]
    float* Ep = smem;            // [32][132] (epilogue reuse)
    float* Vp = smem + 4224;     // [32][132]

    int b = blockIdx.z;
    int tN = blockIdx.x * 128;
    const float* A = g_W1 + (size_t)(b * QKVC + CH) * CH;   // rows 128..383
    const float* B = x + (size_t)b * CH * NSP;
    int tid = threadIdx.x, lane = tid & 31, w = tid >> 5;

    float acc[2][16][4];
#pragma unroll
    for (int mt = 0; mt < 2; mt++)
#pragma unroll
        for (int nt = 0; nt < 16; nt++)
#pragma unroll
            for (int i = 0; i < 4; i++) acc[mt][nt][i] = 0.f;

    for (int k0 = 0; k0 < CH; k0 += 16) {
#pragma unroll
        for (int i = 0; i < 4; i++) {                 // A tile: 1024 float4
            int f = tid + i * 256;
            int r = f >> 2, c4 = (f & 3) * 4;
            float4 v = *reinterpret_cast<const float4*>(&A[r * CH + k0 + c4]);
            As[r * 20 + c4 + 0] = tf32f(v.x);
            As[r * 20 + c4 + 1] = tf32f(v.y);
            As[r * 20 + c4 + 2] = tf32f(v.z);
            As[r * 20 + c4 + 3] = tf32f(v.w);
        }
#pragma unroll
        for (int i = 0; i < 2; i++) {                 // B tile: 512 float4
            int f = tid + i * 256;
            int r = f >> 5, c4 = (f & 31) * 4;
            float4 v = *reinterpret_cast<const float4*>(&B[(size_t)(k0 + r) * NSP + tN + c4]);
            Bs[r * 136 + c4 + 0] = tf32f(v.x);
            Bs[r * 136 + c4 + 1] = tf32f(v.y);
            Bs[r * 136 + c4 + 2] = tf32f(v.z);
            Bs[r * 136 + c4 + 3] = tf32f(v.w);
        }
        __syncthreads();
#pragma unroll
        for (int ks = 0; ks < 16; ks += 8) {
            uint32_t a[2][4];
#pragma unroll
            for (int mt = 0; mt < 2; mt++) {
                int r0 = w * 32 + mt * 16 + (lane >> 2);
                int c  = ks + (lane & 3);
                a[mt][0] = __float_as_uint(As[r0 * 20 + c]);
                a[mt][1] = __float_as_uint(As[(r0 + 8) * 20 + c]);
                a[mt][2] = __float_as_uint(As[r0 * 20 + c + 4]);
                a[mt][3] = __float_as_uint(As[(r0 + 8) * 20 + c + 4]);
            }
#pragma unroll
            for (int nt = 0; nt < 16; nt++) {
                int col = nt * 8 + (lane >> 2);
                uint32_t b0 = __float_as_uint(Bs[(ks + (lane & 3)) * 136 + col]);
                uint32_t b1 = __float_as_uint(Bs[(ks + 4 + (lane & 3)) * 136 + col]);
                mma8(acc[0][nt], a[0][0], a[0][1], a[0][2], a[0][3], b0, b1);
                mma8(acc[1][nt], a[1][0], a[1][1], a[1][2], a[1][3], b0, b1);
            }
        }
        __syncthreads();
    }

    // bias (+exp for k-warps 0..3)
    const float* bias = g_b1 + b * QKVC + CH;
#pragma unroll
    for (int mt = 0; mt < 2; mt++) {
        int r0 = w * 32 + mt * 16 + (lane >> 2);
        float bv0 = bias[r0], bv1 = bias[r0 + 8];
#pragma unroll
        for (int nt = 0; nt < 16; nt++) {
            if (w < 4) {
                acc[mt][nt][0] = __expf(acc[mt][nt][0] + bv0);
                acc[mt][nt][1] = __expf(acc[mt][nt][1] + bv0);
                acc[mt][nt][2] = __expf(acc[mt][nt][2] + bv1);
                acc[mt][nt][3] = __expf(acc[mt][nt][3] + bv1);
            } else {
                acc[mt][nt][0] += bv0; acc[mt][nt][1] += bv0;
                acc[mt][nt][2] += bv1; acc[mt][nt][3] += bv1;
            }
        }
    }

    // per-head partial ctx
    float* pbase = g_ctxp + (size_t)blockIdx.x * CTXSZ;
    for (int h = 0; h < NH; h++) {
        __syncthreads();
        if (w == h || w == h + 4) {
            float* Tp = (w == h) ? Ep : Vp;
#pragma unroll
            for (int mt = 0; mt < 2; mt++) {
                int r0 = mt * 16 + (lane >> 2);
#pragma unroll
                for (int nt = 0; nt < 16; nt++) {
                    int col = nt * 8 + 2 * (lane & 3);
                    Tp[r0 * 132 + col]           = acc[mt][nt][0];
                    Tp[r0 * 132 + col + 1]       = acc[mt][nt][1];
                    Tp[(r0 + 8) * 132 + col]     = acc[mt][nt][2];
                    Tp[(r0 + 8) * 132 + col + 1] = acc[mt][nt][3];
                }
            }
        }
        __syncthreads();
        // ctx mma: M=32(d) x N=32(e), K=128(n). warp -> (mt2, nt2)
        float c4[4] = {0.f, 0.f, 0.f, 0.f};
        int mt2 = w >> 2, nt2 = w & 3;
#pragma unroll
        for (int ks = 0; ks < 128; ks += 8) {
            int ar = mt2 * 16 + (lane >> 2);
            int ac = ks + (lane & 3);
            uint32_t a0 = f2tf(Ep[ar * 132 + ac]);
            uint32_t a1 = f2tf(Ep[(ar + 8) * 132 + ac]);
            uint32_t a2 = f2tf(Ep[ar * 132 + ac + 4]);
            uint32_t a3 = f2tf(Ep[(ar + 8) * 132 + ac + 4]);
            int ec = nt2 * 8 + (lane >> 2);
            uint32_t b0 = f2tf(Vp[ec * 132 + ks + (lane & 3)]);
            uint32_t b1 = f2tf(Vp[ec * 132 + ks + 4 + (lane & 3)]);
            mma8(c4, a0, a1, a2, a3, b0, b1);
        }
        // Z rowsums (8-lane groups, fp32 exact path)
        int d = tid >> 3, nn = tid & 7;
        float z = 0.f;
#pragma unroll
        for (int i = 0; i < 16; i++) z += Ep[d * 132 + nn + 8 * i];
        z += __shfl_xor_sync(0xffffffffu, z, 1);
        z += __shfl_xor_sync(0xffffffffu, z, 2);
        z += __shfl_xor_sync(0xffffffffu, z, 4);

        float* ph = pbase + (size_t)((b * NH + h) * HDIM) * 33;
        int dr = mt2 * 16 + (lane >> 2);
        int ec = nt2 * 8 + 2 * (lane & 3);
        ph[dr * 33 + ec]           = c4[0];
        ph[dr * 33 + ec + 1]       = c4[1];
        ph[(dr + 8) * 33 + ec]     = c4[2];
        ph[(dr + 8) * 33 + ec + 1] = c4[3];
        if (nn == 0) ph[d * 33 + 32] = z;
    }
}

// ---------------- 4) combine ctx partials (deterministic) ----------------
__global__ void combine_k() {
    int t = blockIdx.x * 256 + threadIdx.x;
    if (t >= CTXSZ) return;
    float s = 0.f;
    for (int c = 0; c < NT; c++) s += g_ctxp[(size_t)c * CTXSZ + t];
    g_ctx[t] = s;
}

// ---------------- 5) M = out_w folded through normalized ctx ----------------
__global__ void fold1_k(const float* __restrict__ outw) {
    int o = blockIdx.x, b = blockIdx.y, hd = threadIdx.x;
    int h = hd >> 5, d = hd & 31;
    __shared__ float sOW[CH];
    sOW[hd] = outw[o * CH + hd];
    __syncthreads();
    const float* nm = g_ctx + (size_t)((b * NH + h) * HDIM + d) * 33;
    float acc = 0.f;
#pragma unroll
    for (int e = 0; e < HDIM; e++) acc += sOW[h * HDIM + e] * nm[e];
    g_M[(b * CH + o) * CH + hd] = acc / nm[32];
}

// ---------------- 6) F = M @ Wq',  fb = M @ bq' + out_bias ----------------
__global__ void fold2_k(const float* __restrict__ outb) {
    int o = blockIdx.x, b = blockIdx.y, c = threadIdx.x;
    __shared__ float sM[CH];
    __shared__ float red[CH];
    sM[c] = g_M[(size_t)(b * CH + o) * CH + c];
    __syncthreads();
    const float* Wq = g_W1 + (size_t)b * QKVC * CH;   // q rows 0..127
    float acc = 0.f;
#pragma unroll 8
    for (int k = 0; k < CH; k++) acc += sM[k] * Wq[k * CH + c];
    g_F[(size_t)(b * CH + o) * CH + c] = acc;
    red[c] = sM[c] * g_b1[b * QKVC + c];
    __syncthreads();
    for (int off = 64; off; off >>= 1) {
        if (c < off) red[c] += red[c + off];
        __syncthreads();
    }
    if (c == 0) g_fb[b * CH + o] = red[0] + outb[o];
}

// ---------------- 7) out = F @ x + fb + x ----------------
__global__ void __launch_bounds__(256) gemm1_k(const float* __restrict__ x,
                                               float* __restrict__ out) {
    __shared__ float smem[128 * 20 + 16 * 136];
    float* As = smem;            // [128][20]
    float* Bs = smem + 2560;     // [16][136]

    int b = blockIdx.z;
    int tN = blockIdx.x * 128;
    const float* A = g_F + (size_t)b * CH * CH;
    const float* B = x + (size_t)b * CH * NSP;
    float* Co = out + (size_t)b * CH * NSP;
    int tid = threadIdx.x, lane = tid & 31, w = tid >> 5;

    float acc[16][4];
#pragma unroll
    for (int nt = 0; nt < 16; nt++)
#pragma unroll
        for (int i = 0; i < 4; i++) acc[nt][i] = 0.f;

    for (int k0 = 0; k0 < CH; k0 += 16) {
        {   // A tile: 512 float4
            int f = tid;
            if (f < 512) {
                int r = f >> 2, c4 = (f & 3) * 4;
                float4 v = *reinterpret_cast<const float4*>(&A[r * CH + k0 + c4]);
                As[r * 20 + c4 + 0] = tf32f(v.x);
                As[r * 20 + c4 + 1] = tf32f(v.y);
                As[r * 20 + c4 + 2] = tf32f(v.z);
                As[r * 20 + c4 + 3] = tf32f(v.w);
            }
            int f2 = tid + 256;
            int r = f2 >> 2, c4 = (f2 & 3) * 4;
            float4 v = *reinterpret_cast<const float4*>(&A[r * CH + k0 + c4]);
            As[r * 20 + c4 + 0] = tf32f(v.x);
            As[r * 20 + c4 + 1] = tf32f(v.y);
            As[r * 20 + c4 + 2] = tf32f(v.z);
            As[r * 20 + c4 + 3] = tf32f(v.w);
        }
#pragma unroll
        for (int i = 0; i < 2; i++) {   // B tile: 512 float4
            int f = tid + i * 256;
            int r = f >> 5, c4 = (f & 31) * 4;
            float4 v = *reinterpret_cast<const float4*>(&B[(size_t)(k0 + r) * NSP + tN + c4]);
            Bs[r * 136 + c4 + 0] = tf32f(v.x);
            Bs[r * 136 + c4 + 1] = tf32f(v.y);
            Bs[r * 136 + c4 + 2] = tf32f(v.z);
            Bs[r * 136 + c4 + 3] = tf32f(v.w);
        }
        __syncthreads();
#pragma unroll
        for (int ks = 0; ks < 16; ks += 8) {
            int r0 = w * 16 + (lane >> 2);
            int c  = ks + (lane & 3);
            uint32_t a0 = __float_as_uint(As[r0 * 20 + c]);
            uint32_t a1 = __float_as_uint(As[(r0 + 8) * 20 + c]);
            uint32_t a2 = __float_as_uint(As[r0 * 20 + c + 4]);
            uint32_t a3 = __float_as_uint(As[(r0 + 8) * 20 + c + 4]);
#pragma unroll
            for (int nt = 0; nt < 16; nt++) {
                int col = nt * 8 + (lane >> 2);
                uint32_t b0 = __float_as_uint(Bs[(ks + (lane & 3)) * 136 + col]);
                uint32_t b1 = __float_as_uint(Bs[(ks + 4 + (lane & 3)) * 136 + col]);
                mma8(acc[nt], a0, a1, a2, a3, b0, b1);
            }
        }
        __syncthreads();
    }

    int r0 = w * 16 + (lane >> 2);
    float bv0 = g_fb[b * CH + r0], bv1 = g_fb[b * CH + r0 + 8];
#pragma unroll
    for (int nt = 0; nt < 16; nt++) {
        int col = nt * 8 + 2 * (lane & 3);
        size_t o0 = (size_t)r0 * NSP + tN + col;
        size_t o1 = (size_t)(r0 + 8) * NSP + tN + col;
        float2 x0 = *reinterpret_cast<const float2*>(&B[o0]);
        float2 x1 = *reinterpret_cast<const float2*>(&B[o1]);
        float2 r0v = { acc[nt][0] + bv0 + x0.x, acc[nt][1] + bv0 + x0.y };
        float2 r1v = { acc[nt][2] + bv1 + x1.x, acc[nt][3] + bv1 + x1.y };
        *reinterpret_cast<float2*>(&Co[o0]) = r0v;
        *reinterpret_cast<float2*>(&Co[o1]) = r1v;
    }
}

// ---------------- launch ----------------
extern "C" void kernel_launch(void* const* d_in, const int* in_sizes, int n_in,
                              void* d_out, int out_size) {
    (void)in_sizes; (void)n_in; (void)out_size;
    const float* x    = (const float*)d_in[0];
    const float* gnw  = (const float*)d_in[1];
    const float* gnb  = (const float*)d_in[2];
    const float* qkvw = (const float*)d_in[3];
    const float* outw = (const float*)d_in[4];
    const float* outb = (const float*)d_in[5];
    float* out = (float*)d_out;

    reduce_k<<<NB * GRP * RED_CHUNKS, 256>>>(x);
    prep_k<<<dim3(QKVC, NB), CH>>>(qkvw, gnw, gnb);
    gemm0_k<<<dim3(NT, 1, NB), 256>>>(x);
    combine_k<<<(CTXSZ + 255) / 256, 256>>>();
    fold1_k<<<dim3(CH, NB), CH>>>(outw);
    fold2_k<<<dim3(CH, NB), CH>>>(outb);
    gemm1_k<<<dim3(NT, 1, NB), 256>>>(x, out);
}